// round 17
// baseline (speedup 1.0000x reference)
#include <cuda_runtime.h>
#include <cstdint>

// Problem constants
#define K_CODES 1024
#define D_DIM   256
#define HW      1024      // 32*32 pixels per image
#define NPIX    65536

// Tiling: TILE_P=64 px/CTA, TILE_K=128 codes per k-tile, CHUNK_D=32
#define TILE_P     64
#define TILE_K     128
#define CHUNK_D    32
#define NUM_KT     (K_CODES / TILE_K)            // 8
#define CHUNKS_PER_KT (D_DIM / CHUNK_D)          // 8
#define TOTAL_CHUNKS  (NUM_KT * CHUNKS_PER_KT)   // 64

#define ZS_STRIDE  260    // 256 + 4 pad (16B-aligned rows)
#define ES_STRIDE  36     // 32 + 4 pad (16B-aligned; (tx+s)%8 slot spread)

// smem byte offsets (per CTA: ~111.9 KB -> 2 CTAs/SM)
#define SM_ZS    0
#define SM_ZS_SZ (TILE_P * ZS_STRIDE * 4)                 // 66560
#define SM_ES0   (SM_ZS + SM_ZS_SZ)
#define SM_ES_SZ (TILE_K * ES_STRIDE * 4)                 // 18432
#define SM_ES1   (SM_ES0 + SM_ES_SZ)
#define SM_RED   (SM_ES1 + SM_ES_SZ)                      // 103424
#define SM_RED_SZ (TILE_P * 16 * 8)                       // 8192
#define SM_NZ    (SM_RED + SM_RED_SZ)                     // 111616
#define SM_TOTAL (SM_NZ + TILE_P * 4)                     // 111872

__device__ float g_norme[K_CODES];

// ---------------- helpers ----------------

__device__ __forceinline__ unsigned long long ffma2(unsigned long long a,
                                                    unsigned long long b,
                                                    unsigned long long c) {
    unsigned long long d;
    asm("fma.rn.f32x2 %0, %1, %2, %3;" : "=l"(d) : "l"(a), "l"(b), "l"(c));
    return d;
}

__device__ __forceinline__ void cp_async16(uint32_t smem_addr, const float* gptr) {
    asm volatile("cp.async.cg.shared.global [%0], [%1], 16;\n"
                 :: "r"(smem_addr), "l"(gptr));
}
__device__ __forceinline__ void cp_commit() {
    asm volatile("cp.async.commit_group;\n");
}
template <int N>
__device__ __forceinline__ void cp_wait() {
    asm volatile("cp.async.wait_group %0;\n" :: "n"(N));
}

// Monotone float -> uint mapping; pack with index so u64-min == (score, then lowest index)
__device__ __forceinline__ unsigned long long pack_score(float s, int k) {
    unsigned u = __float_as_uint(s);
    u = ((int)u < 0) ? ~u : (u | 0x80000000u);
    return ((unsigned long long)u << 32) | (unsigned)k;
}

__device__ __forceinline__ unsigned long long umin64(unsigned long long a,
                                                     unsigned long long b) {
    return a < b ? a : b;
}

// ---------------- kernels ----------------

__global__ void norme_kernel(const float* __restrict__ emb) {
    int k = blockIdx.x * blockDim.x + threadIdx.x;
    if (k >= K_CODES) return;
    const float4* row = reinterpret_cast<const float4*>(emb + (size_t)k * D_DIM);
    float4 a = make_float4(0.f, 0.f, 0.f, 0.f);
#pragma unroll
    for (int i = 0; i < D_DIM / 4; i++) {
        float4 v = row[i];
        a.x = fmaf(v.x, v.x, a.x);
        a.y = fmaf(v.y, v.y, a.y);
        a.z = fmaf(v.z, v.z, a.z);
        a.w = fmaf(v.w, v.w, a.w);
    }
    g_norme[k] = (a.x + a.y) + (a.z + a.w);
}

__global__ void __launch_bounds__(256, 2)
vq_argmin_kernel(const float* __restrict__ z,
                 const float* __restrict__ emb,
                 float* __restrict__ out) {
    extern __shared__ char smem[];
    float* zs  = reinterpret_cast<float*>(smem + SM_ZS);    // [64][260]
    float* es0 = reinterpret_cast<float*>(smem + SM_ES0);   // [128][36]
    float* es1 = reinterpret_cast<float*>(smem + SM_ES1);
    unsigned long long* red = reinterpret_cast<unsigned long long*>(smem + SM_RED); // [64][16]
    float* nz  = reinterpret_cast<float*>(smem + SM_NZ);    // [64]

    const int tid  = threadIdx.x;
    const int tile = blockIdx.x;
    const int b    = tile >> 4;            // image index (16 tiles per image)
    const int p0   = (tile & 15) << 6;

    const float* zb = z + (size_t)b * D_DIM * HW + p0;

    // ---- load z tile transposed: zs[p][d] = z[b][d][p0+p] ----
    {
        int p  = tid & 63;
        int dg = tid >> 6;   // 0..3
#pragma unroll
        for (int r = 0; r < 64; r++) {
            int d = r * 4 + dg;
            zs[p * ZS_STRIDE + d] = zb[(size_t)d * HW + p];
        }
    }
    __syncthreads();

    // ---- per-pixel ||z||^2 ----
    if (tid < 64) {
        const float4* row = reinterpret_cast<const float4*>(zs + tid * ZS_STRIDE);
        float4 a = make_float4(0.f, 0.f, 0.f, 0.f);
#pragma unroll
        for (int i = 0; i < D_DIM / 4; i++) {
            float4 v = row[i];
            a.x = fmaf(v.x, v.x, a.x);
            a.y = fmaf(v.y, v.y, a.y);
            a.z = fmaf(v.z, v.z, a.z);
            a.w = fmaf(v.w, v.w, a.w);
        }
        nz[tid] = (a.x + a.y) + (a.z + a.w);
    }

    const int tx = tid & 15;   // code group: codes {tx + 16*i}, i=0..7, of k-tile
    const int ty = tid >> 4;   // pixel group: pixels 4*ty .. 4*ty+3

    // e-chunk loader: chunk c -> (kt = c>>3, dc = c&7); 128 codes x 32 floats = 16KB
    auto issue_chunk = [&](int c, float* dst_base) {
        const int kt = c >> 3, dc = c & 7;
        const int row0 = tid >> 1;          // 0..127
        const int half = tid & 1;           // 0..1 -> 16-float half of the 32-float row
        const float* src = emb + (size_t)((kt << 7) + row0) * D_DIM + (dc << 5) + (half << 4);
        float* dst = dst_base + row0 * ES_STRIDE + (half << 4);
        uint32_t saddr = (uint32_t)__cvta_generic_to_shared(dst);
#pragma unroll
        for (int j = 0; j < 4; j++) cp_async16(saddr + j * 16, src + j * 4);
        cp_commit();
    };

    unsigned long long acc[8][4];          // [code i][pixel j]
    unsigned long long best[4] = {~0ull, ~0ull, ~0ull, ~0ull};   // per pixel j

    issue_chunk(0, es0);

    for (int c = 0; c < TOTAL_CHUNKS; c++) {
        cp_wait<0>();
        __syncthreads();   // chunk c visible; all warps done with buffer being refilled

        if (c + 1 < TOTAL_CHUNKS)
            issue_chunk(c + 1, ((c + 1) & 1) ? es1 : es0);   // overlaps compute below

        const float* eb = (c & 1) ? es1 : es0;

        if ((c & 7) == 0) {
#pragma unroll
            for (int i = 0; i < 8; i++)
#pragma unroll
                for (int j = 0; j < 4; j++) acc[i][j] = 0ull;
        }

        const int dbase = (c & 7) << 5;

#pragma unroll
        for (int s = 0; s < 8; s++) {
            const int d = dbase + (s << 2);

            ulonglong2 zf[4];
#pragma unroll
            for (int j = 0; j < 4; j++)
                zf[j] = *reinterpret_cast<const ulonglong2*>(
                    zs + (ty * 4 + j) * ZS_STRIDE + d);

            // ---- first half: codes i=0..3 (ef live range limited to 16 regs) ----
            {
                ulonglong2 ef[4];
#pragma unroll
                for (int i = 0; i < 4; i++)
                    ef[i] = *reinterpret_cast<const ulonglong2*>(
                        eb + (i * 16 + tx) * ES_STRIDE + (s << 2));
#pragma unroll
                for (int i = 0; i < 4; i++)
#pragma unroll
                    for (int j = 0; j < 4; j++)
                        acc[i][j] = ffma2(zf[j].x, ef[i].x, acc[i][j]);
#pragma unroll
                for (int i = 0; i < 4; i++)
#pragma unroll
                    for (int j = 0; j < 4; j++)
                        acc[i][j] = ffma2(zf[j].y, ef[i].y, acc[i][j]);
            }
            // ---- second half: codes i=4..7 ----
            {
                ulonglong2 ef[4];
#pragma unroll
                for (int i = 0; i < 4; i++)
                    ef[i] = *reinterpret_cast<const ulonglong2*>(
                        eb + ((i + 4) * 16 + tx) * ES_STRIDE + (s << 2));
#pragma unroll
                for (int i = 0; i < 4; i++)
#pragma unroll
                    for (int j = 0; j < 4; j++)
                        acc[i + 4][j] = ffma2(zf[j].x, ef[i].x, acc[i + 4][j]);
#pragma unroll
                for (int i = 0; i < 4; i++)
#pragma unroll
                    for (int j = 0; j < 4; j++)
                        acc[i + 4][j] = ffma2(zf[j].y, ef[i].y, acc[i + 4][j]);
            }
        }

        if ((c & 7) == 7) {   // k-tile complete: fold argmin IN REGISTERS (no barrier)
            const int kt = c >> 3;
#pragma unroll
            for (int j = 0; j < 4; j++) {
                const float nzp = nz[ty * 4 + j];
#pragma unroll
                for (int i = 0; i < 8; i++) {
                    float lo = __uint_as_float((unsigned)(acc[i][j] & 0xFFFFFFFFull));
                    float hi = __uint_as_float((unsigned)(acc[i][j] >> 32));
                    float dot = __fadd_rn(lo, hi);
                    // reference rounding: (||z||^2 - 2*(z.e)) + ||e||^2, no contraction
                    float t  = __fsub_rn(nzp, __fmul_rn(2.0f, dot));
                    int code = (kt << 7) + i * 16 + tx;
                    float sc = __fadd_rn(t, g_norme[code]);
                    best[j] = umin64(best[j], pack_score(sc, code));
                }
            }
        }
    }

    // ---- single final cross-thread reduction ----
#pragma unroll
    for (int j = 0; j < 4; j++)
        red[(ty * 4 + j) * 16 + tx] = best[j];
    __syncthreads();

    if (tid < 64) {
        unsigned long long m = red[tid * 16];
#pragma unroll
        for (int x = 1; x < 16; x++) m = umin64(m, red[tid * 16 + x]);
        out[tile * 64 + tid] = (float)(int)(m & 0xFFFFFFFFull);   // float32 output
    }
}

// ---------------- launch ----------------

extern "C" void kernel_launch(void* const* d_in, const int* in_sizes, int n_in,
                              void* d_out, int out_size) {
    // Dispatch inputs BY SIZE — robust to metadata ordering.
    const float* z   = (const float*)d_in[0];
    const float* emb = (const float*)d_in[1];
    if (n_in >= 2 && in_sizes[0] == K_CODES * D_DIM) {
        emb = (const float*)d_in[0];
        z   = (const float*)d_in[1];
    }
    float* out = (float*)d_out;   // [64,32,32] indices as float32

    cudaFuncSetAttribute(vq_argmin_kernel,
                         cudaFuncAttributeMaxDynamicSharedMemorySize, SM_TOTAL);

    norme_kernel<<<(K_CODES + 255) / 256, 256>>>(emb);
    vq_argmin_kernel<<<NPIX / TILE_P, 256, SM_TOTAL>>>(z, emb, out);
}